// round 3
// baseline (speedup 1.0000x reference)
#include <cuda_runtime.h>
#include <cuda_bf16.h>

// ---------------- constants (match problem shape) ----------------
#define NMAX      100000
#define NNZMAX    3200000
#define DIMC      256

// ---------------- device scratch (no allocations allowed) ----------------
__device__ static float g_Hn[NMAX * DIMC];   // SpMM result per hop
__device__ static float g_HA[NMAX * DIMC];   // H after hop 0
__device__ static float g_HB[NMAX * DIMC];   // H after hop 1
__device__ static int2  g_edges[NNZMAX];     // CSR: (col, val-as-bits) sorted by row
__device__ static int   g_cnt[NMAX];
__device__ static int   g_rowptr[NMAX + 1];
__device__ static int   g_woff[NMAX];

// ---------------- CSR build ----------------
__global__ void zero_cnt_kernel(int* cnt, int N) {
    int i = blockIdx.x * blockDim.x + threadIdx.x;
    if (i < N) cnt[i] = 0;
}

__global__ void hist_kernel(const int* __restrict__ rows, int* cnt, int nnz) {
    int e = blockIdx.x * blockDim.x + threadIdx.x;
    if (e < nnz) atomicAdd(&cnt[rows[e]], 1);
}

// single-block exclusive scan over N counts (1024 threads, sequential chunks)
__global__ void scan_kernel(const int* __restrict__ cnt, int* row_ptr, int* woff,
                            int N, int nnz) {
    __shared__ int wsum[32];
    int tid = threadIdx.x;                 // 0..1023
    int CH = (N + 1023) / 1024;
    int base = tid * CH;
    int s = 0;
    for (int j = 0; j < CH; j++) {
        int i = base + j;
        if (i < N) s += cnt[i];
    }
    // warp inclusive scan
    int v = s;
    #pragma unroll
    for (int d = 1; d < 32; d <<= 1) {
        int n = __shfl_up_sync(0xffffffffu, v, d);
        if ((tid & 31) >= d) v += n;
    }
    if ((tid & 31) == 31) wsum[tid >> 5] = v;
    __syncthreads();
    if (tid < 32) {
        int w = wsum[tid];
        #pragma unroll
        for (int d = 1; d < 32; d <<= 1) {
            int n = __shfl_up_sync(0xffffffffu, w, d);
            if (tid >= d) w += n;
        }
        wsum[tid] = w;
    }
    __syncthreads();
    int warp = tid >> 5;
    int excl = (v - s) + (warp > 0 ? wsum[warp - 1] : 0);
    int run = excl;
    for (int j = 0; j < CH; j++) {
        int i = base + j;
        if (i < N) {
            row_ptr[i] = run;
            woff[i]    = run;
            run += cnt[i];
        }
    }
    if (tid == 0) row_ptr[N] = nnz;
}

__global__ void scatter_kernel(const int* __restrict__ rows,
                               const int* __restrict__ cols,
                               const float* __restrict__ vals,
                               int* woff, int2* edges, int nnz) {
    int e = blockIdx.x * blockDim.x + threadIdx.x;
    if (e < nnz) {
        int r = rows[e];
        int p = atomicAdd(&woff[r], 1);
        edges[p] = make_int2(cols[e], __float_as_int(vals[e]));
    }
}

// ---------------- SpMM: warp per row, CSR, L2-resident gather ----------------
__global__ void spmm_kernel(const float* __restrict__ H,
                            const int* __restrict__ row_ptr,
                            const int2* __restrict__ edges,
                            float* __restrict__ Hn, int N) {
    int warp = (blockIdx.x * blockDim.x + threadIdx.x) >> 5;
    int lane = threadIdx.x & 31;
    if (warp >= N) return;
    int start = row_ptr[warp];
    int end   = row_ptr[warp + 1];

    float4 acc0 = make_float4(0.f, 0.f, 0.f, 0.f);
    float4 acc1 = make_float4(0.f, 0.f, 0.f, 0.f);

    for (int e0 = start; e0 < end; e0 += 32) {
        int idx = e0 + lane;
        int2 ed = make_int2(0, 0);
        if (idx < end) ed = edges[idx];
        int cnt = min(32, end - e0);
        for (int j = 0; j < cnt; j++) {
            int   col = __shfl_sync(0xffffffffu, ed.x, j);
            float val = __int_as_float(__shfl_sync(0xffffffffu, ed.y, j));
            const float4* hp = (const float4*)(H + (size_t)col * DIMC);
            float4 h0 = hp[lane];
            float4 h1 = hp[32 + lane];
            acc0.x += val * h0.x; acc0.y += val * h0.y;
            acc0.z += val * h0.z; acc0.w += val * h0.w;
            acc1.x += val * h1.x; acc1.y += val * h1.y;
            acc1.z += val * h1.z; acc1.w += val * h1.w;
        }
    }
    float4* out = (float4*)(Hn + (size_t)warp * DIMC);
    out[lane]      = acc0;
    out[32 + lane] = acc1;
}

// ---------------- fused GEMM: out = Hn@Wn^T + Hc@Ws^T + (bn+bs), optional ELU -----
// C[M,256] with K=512 split: k<256 -> (Hn, Wn), k>=256 -> (Hc, Ws)
// tile 128x128x16, 256 threads, 8x8 register micro-tile
__global__ __launch_bounds__(256, 2)
void gemm_fused_kernel(const float* __restrict__ Hn, const float* __restrict__ Hc,
                       const float* __restrict__ Wn, const float* __restrict__ Ws,
                       const float* __restrict__ bn, const float* __restrict__ bs,
                       float* __restrict__ out, int M, int doElu) {
    __shared__ float As[16][132];
    __shared__ float Bs[16][132];

    int tid = threadIdx.x;
    int tx = tid & 15;      // 0..15 -> col group
    int ty = tid >> 4;      // 0..15 -> row group
    int rowBase = blockIdx.x * 128;
    int colBase = blockIdx.y * 128;

    float acc[8][8];
    #pragma unroll
    for (int i = 0; i < 8; i++)
        #pragma unroll
        for (int j = 0; j < 8; j++) acc[i][j] = 0.f;

    for (int t = 0; t < 32; t++) {
        int kbase = t * 16;
        const float* Asrc = (kbase < 256) ? Hn : Hc;
        const float* Wsrc = (kbase < 256) ? Wn : Ws;
        int kOff = kbase & 255;

        // load A tile: 128 rows x 16 k, float4 along k
        #pragma unroll
        for (int it = 0; it < 2; it++) {
            int idx = tid + it * 256;
            int r  = idx >> 2;      // 0..127
            int k4 = idx & 3;       // 0..3
            float4 v = make_float4(0.f, 0.f, 0.f, 0.f);
            int grow = rowBase + r;
            if (grow < M)
                v = *(const float4*)(Asrc + (size_t)grow * DIMC + kOff + k4 * 4);
            As[k4 * 4 + 0][r] = v.x;
            As[k4 * 4 + 1][r] = v.y;
            As[k4 * 4 + 2][r] = v.z;
            As[k4 * 4 + 3][r] = v.w;
        }
        // load B tile: B(k,j) = W[j*256+k] (row-major over k)
        #pragma unroll
        for (int it = 0; it < 2; it++) {
            int idx = tid + it * 256;
            int j  = idx >> 2;      // 0..127
            int k4 = idx & 3;
            float4 v = *(const float4*)(Wsrc + (size_t)(colBase + j) * DIMC + kOff + k4 * 4);
            Bs[k4 * 4 + 0][j] = v.x;
            Bs[k4 * 4 + 1][j] = v.y;
            Bs[k4 * 4 + 2][j] = v.z;
            Bs[k4 * 4 + 3][j] = v.w;
        }
        __syncthreads();

        #pragma unroll
        for (int kk = 0; kk < 16; kk++) {
            float ra[8], rb[8];
            #pragma unroll
            for (int i = 0; i < 8; i++) ra[i] = As[kk][ty * 8 + i];
            #pragma unroll
            for (int j = 0; j < 8; j++) rb[j] = Bs[kk][tx * 8 + j];
            #pragma unroll
            for (int i = 0; i < 8; i++)
                #pragma unroll
                for (int j = 0; j < 8; j++)
                    acc[i][j] += ra[i] * rb[j];
        }
        __syncthreads();
    }

    // epilogue: bias + optional ELU
    #pragma unroll
    for (int i = 0; i < 8; i++) {
        int grow = rowBase + ty * 8 + i;
        if (grow >= M) continue;
        #pragma unroll
        for (int j = 0; j < 8; j++) {
            int gcol = colBase + tx * 8 + j;
            float v = acc[i][j] + bn[gcol] + bs[gcol];
            if (doElu && v < 0.f) v = expm1f(v);
            out[(size_t)grow * DIMC + gcol] = v;
        }
    }
}

// ---------------- launch ----------------
extern "C" void kernel_launch(void* const* d_in, const int* in_sizes, int n_in,
                              void* d_out, int out_size) {
    const float* m    = (const float*)d_in[0];
    const float* vals = (const float*)d_in[1];
    const float* Wn   = (const float*)d_in[2];
    const float* bn   = (const float*)d_in[3];
    const float* Ws   = (const float*)d_in[4];
    const float* bs   = (const float*)d_in[5];
    const int*   rows = (const int*)d_in[6];   // int32: JAX default x64-disabled
    const int*   cols = (const int*)d_in[7];

    int N    = in_sizes[0] / DIMC;
    int nnz  = in_sizes[1];
    int hops = in_sizes[2] / (DIMC * DIMC);

    float *Hn, *HA, *HB;
    int *cnt, *rowptr, *woff;
    int2* edges;
    cudaGetSymbolAddress((void**)&Hn,     g_Hn);
    cudaGetSymbolAddress((void**)&HA,     g_HA);
    cudaGetSymbolAddress((void**)&HB,     g_HB);
    cudaGetSymbolAddress((void**)&edges,  g_edges);
    cudaGetSymbolAddress((void**)&cnt,    g_cnt);
    cudaGetSymbolAddress((void**)&rowptr, g_rowptr);
    cudaGetSymbolAddress((void**)&woff,   g_woff);

    // --- build CSR once, reuse across hops ---
    zero_cnt_kernel<<<(N + 255) / 256, 256>>>(cnt, N);
    hist_kernel<<<(nnz + 255) / 256, 256>>>(rows, cnt, nnz);
    scan_kernel<<<1, 1024>>>(cnt, rowptr, woff, N, nnz);
    scatter_kernel<<<(nnz + 255) / 256, 256>>>(rows, cols, vals, woff, edges, nnz);

    // --- hop loop ---
    float* out0 = (float*)d_out;
    int spmm_blocks = (N * 32 + 255) / 256;     // warp per row
    dim3 ggrid((N + 127) / 128, DIMC / 128);

    const float* Hcur = m;
    for (int i = 0; i < hops; i++) {
        spmm_kernel<<<spmm_blocks, 256>>>(Hcur, rowptr, edges, Hn, N);
        float* dst = (i == hops - 1) ? out0 : (i == 0 ? HA : HB);
        gemm_fused_kernel<<<ggrid, 256>>>(Hn, Hcur,
                                          Wn + (size_t)i * DIMC * DIMC,
                                          Ws + (size_t)i * DIMC * DIMC,
                                          bn + (size_t)i * DIMC,
                                          bs + (size_t)i * DIMC,
                                          dst, N, i != hops - 1);
        Hcur = dst;
    }
}

// round 4
// speedup vs baseline: 1.9880x; 1.9880x over previous
#include <cuda_runtime.h>
#include <cuda_bf16.h>

// ---------------- constants (match problem shape) ----------------
#define NMAX      100000
#define NNZMAX    3200000
#define DIMC      256

// ---------------- device scratch (no allocations allowed) ----------------
__device__ static float g_Hn[NMAX * DIMC];   // SpMM result per hop
__device__ static float g_HA[NMAX * DIMC];   // H after hop 0
__device__ static float g_HB[NMAX * DIMC];   // H after hop 1
__device__ static int2  g_edges[NNZMAX];     // CSR: (col, val-as-bits) sorted by row
__device__ static int   g_cnt[NMAX];
__device__ static int   g_rowptr[NMAX + 1];
__device__ static int   g_woff[NMAX];

// ---------------- CSR build ----------------
__global__ void zero_cnt_kernel(int* cnt, int N) {
    int i = blockIdx.x * blockDim.x + threadIdx.x;
    if (i < N) cnt[i] = 0;
}

__global__ void hist_kernel(const int* __restrict__ rows, int* cnt, int nnz) {
    int e = blockIdx.x * blockDim.x + threadIdx.x;
    if (e < nnz) atomicAdd(&cnt[rows[e]], 1);
}

// single-block exclusive scan over N counts (1024 threads, sequential chunks)
__global__ void scan_kernel(const int* __restrict__ cnt, int* row_ptr, int* woff,
                            int N, int nnz) {
    __shared__ int wsum[32];
    int tid = threadIdx.x;
    int CH = (N + 1023) / 1024;
    int base = tid * CH;
    int s = 0;
    for (int j = 0; j < CH; j++) {
        int i = base + j;
        if (i < N) s += cnt[i];
    }
    int v = s;
    #pragma unroll
    for (int d = 1; d < 32; d <<= 1) {
        int n = __shfl_up_sync(0xffffffffu, v, d);
        if ((tid & 31) >= d) v += n;
    }
    if ((tid & 31) == 31) wsum[tid >> 5] = v;
    __syncthreads();
    if (tid < 32) {
        int w = wsum[tid];
        #pragma unroll
        for (int d = 1; d < 32; d <<= 1) {
            int n = __shfl_up_sync(0xffffffffu, w, d);
            if (tid >= d) w += n;
        }
        wsum[tid] = w;
    }
    __syncthreads();
    int warp = tid >> 5;
    int excl = (v - s) + (warp > 0 ? wsum[warp - 1] : 0);
    int run = excl;
    for (int j = 0; j < CH; j++) {
        int i = base + j;
        if (i < N) {
            row_ptr[i] = run;
            woff[i]    = run;
            run += cnt[i];
        }
    }
    if (tid == 0) row_ptr[N] = nnz;
}

__global__ void scatter_kernel(const int* __restrict__ rows,
                               const int* __restrict__ cols,
                               const float* __restrict__ vals,
                               int* woff, int2* edges, int nnz) {
    int e = blockIdx.x * blockDim.x + threadIdx.x;
    if (e < nnz) {
        int r = rows[e];
        int p = atomicAdd(&woff[r], 1);
        edges[p] = make_int2(cols[e], __float_as_int(vals[e]));
    }
}

// ---------------- SpMM: warp per row, CSR, L2-resident gather ----------------
__global__ void spmm_kernel(const float* __restrict__ H,
                            const int* __restrict__ row_ptr,
                            const int2* __restrict__ edges,
                            float* __restrict__ Hn, int N) {
    int warp = (blockIdx.x * blockDim.x + threadIdx.x) >> 5;
    int lane = threadIdx.x & 31;
    if (warp >= N) return;
    int start = row_ptr[warp];
    int end   = row_ptr[warp + 1];

    float4 acc0 = make_float4(0.f, 0.f, 0.f, 0.f);
    float4 acc1 = make_float4(0.f, 0.f, 0.f, 0.f);

    for (int e0 = start; e0 < end; e0 += 32) {
        int idx = e0 + lane;
        int2 ed = make_int2(0, 0);
        if (idx < end) ed = edges[idx];
        int cnt = min(32, end - e0);
        for (int j = 0; j < cnt; j++) {
            int   col = __shfl_sync(0xffffffffu, ed.x, j);
            float val = __int_as_float(__shfl_sync(0xffffffffu, ed.y, j));
            const float4* hp = (const float4*)(H + (size_t)col * DIMC);
            float4 h0 = hp[lane];
            float4 h1 = hp[32 + lane];
            acc0.x += val * h0.x; acc0.y += val * h0.y;
            acc0.z += val * h0.z; acc0.w += val * h0.w;
            acc1.x += val * h1.x; acc1.y += val * h1.y;
            acc1.z += val * h1.z; acc1.w += val * h1.w;
        }
    }
    float4* out = (float4*)(Hn + (size_t)warp * DIMC);
    out[lane]      = acc0;
    out[32 + lane] = acc1;
}

// ---------------- tf32 tensor-core GEMM ----------------
// out[M,256] = Hn@Wn^T + Hc@Ws^T + (bn+bs), optional ELU.
// K=512 logical (k<256 -> Hn/Wn, else Hc/Ws). Block tile 128x128, 4 warps
// (2x2), warp tile 64x64, BK=16, cp.async double-buffered smem.
#define GSTR 20   // smem row stride in words (16 k + 4 pad) -> conflict-free frags

__device__ __forceinline__ unsigned f2tf32(float x) {
    unsigned r;
    asm("cvt.rna.tf32.f32 %0, %1;" : "=r"(r) : "f"(x));
    return r;
}

__global__ __launch_bounds__(128)
void gemm_tf32_kernel(const float* __restrict__ Hn, const float* __restrict__ Hc,
                      const float* __restrict__ Wn, const float* __restrict__ Ws,
                      const float* __restrict__ bn, const float* __restrict__ bs,
                      float* __restrict__ out, int M, int doElu) {
    __shared__ float As[2][128 * GSTR];
    __shared__ float Bs[2][128 * GSTR];

    int tid  = threadIdx.x;
    int lane = tid & 31;
    int wid  = tid >> 5;
    int grp  = lane >> 2;       // 0..7
    int tig  = lane & 3;        // 0..3
    int warpM = wid >> 1;       // 0..1
    int warpN = wid & 1;        // 0..1
    int rowBase = blockIdx.x * 128;
    int colBase = blockIdx.y * 128;

    int lf = tid & 3;           // k-float4 slot (0..3 -> k 0..15)
    int lr = tid >> 2;          // 0..31 row base

    float c[4][8][4];
    #pragma unroll
    for (int mi = 0; mi < 4; mi++)
        #pragma unroll
        for (int ni = 0; ni < 8; ni++)
            #pragma unroll
            for (int r = 0; r < 4; r++) c[mi][ni][r] = 0.f;

    // issue cp.async loads for k-slab `it` into stage it&1
    auto issue = [&](int it) {
        int k0 = it * 16;
        const float* Asrc = (k0 < 256) ? Hn : Hc;
        const float* Wsrc = (k0 < 256) ? Wn : Ws;
        int kOff = k0 & 255;
        int st = it & 1;
        #pragma unroll
        for (int i = 0; i < 4; i++) {
            int row = lr + 32 * i;
            int grow = rowBase + row;
            int ok = (grow < M);
            const float* asrc = Asrc + (size_t)(ok ? grow : 0) * DIMC + kOff + lf * 4;
            unsigned adst = (unsigned)__cvta_generic_to_shared(&As[st][row * GSTR + lf * 4]);
            int asz = ok ? 16 : 0;
            asm volatile("cp.async.cg.shared.global [%0], [%1], 16, %2;\n"
                         :: "r"(adst), "l"(asrc), "r"(asz));
            const float* bsrc = Wsrc + (size_t)(colBase + row) * DIMC + kOff + lf * 4;
            unsigned bdst = (unsigned)__cvta_generic_to_shared(&Bs[st][row * GSTR + lf * 4]);
            asm volatile("cp.async.cg.shared.global [%0], [%1], 16, %2;\n"
                         :: "r"(bdst), "l"(bsrc), "r"(16));
        }
        asm volatile("cp.async.commit_group;\n");
    };

    issue(0);

    for (int it = 0; it < 32; it++) {
        if (it + 1 < 32) {
            issue(it + 1);
            asm volatile("cp.async.wait_group 1;\n");
        } else {
            asm volatile("cp.async.wait_group 0;\n");
        }
        __syncthreads();

        int st = it & 1;
        #pragma unroll
        for (int kk = 0; kk < 2; kk++) {
            unsigned a[4][4], b[8][2];
            int k = kk * 8 + tig;
            #pragma unroll
            for (int mi = 0; mi < 4; mi++) {
                int m0 = warpM * 64 + mi * 16 + grp;
                a[mi][0] = f2tf32(As[st][m0 * GSTR + k]);
                a[mi][1] = f2tf32(As[st][(m0 + 8) * GSTR + k]);
                a[mi][2] = f2tf32(As[st][m0 * GSTR + k + 4]);
                a[mi][3] = f2tf32(As[st][(m0 + 8) * GSTR + k + 4]);
            }
            #pragma unroll
            for (int ni = 0; ni < 8; ni++) {
                int n0 = warpN * 64 + ni * 8 + grp;
                b[ni][0] = f2tf32(Bs[st][n0 * GSTR + k]);
                b[ni][1] = f2tf32(Bs[st][n0 * GSTR + k + 4]);
            }
            #pragma unroll
            for (int mi = 0; mi < 4; mi++)
                #pragma unroll
                for (int ni = 0; ni < 8; ni++) {
                    asm volatile(
                        "mma.sync.aligned.m16n8k8.row.col.f32.tf32.tf32.f32 "
                        "{%0,%1,%2,%3}, {%4,%5,%6,%7}, {%8,%9}, {%0,%1,%2,%3};\n"
                        : "+f"(c[mi][ni][0]), "+f"(c[mi][ni][1]),
                          "+f"(c[mi][ni][2]), "+f"(c[mi][ni][3])
                        : "r"(a[mi][0]), "r"(a[mi][1]), "r"(a[mi][2]), "r"(a[mi][3]),
                          "r"(b[ni][0]), "r"(b[ni][1]));
                }
        }
        __syncthreads();
    }

    // epilogue: bias + optional ELU
    #pragma unroll
    for (int mi = 0; mi < 4; mi++) {
        #pragma unroll
        for (int r = 0; r < 2; r++) {
            int grow = rowBase + warpM * 64 + mi * 16 + grp + r * 8;
            if (grow >= M) continue;
            #pragma unroll
            for (int ni = 0; ni < 8; ni++) {
                int gcol = colBase + warpN * 64 + ni * 8 + tig * 2;
                float v0 = c[mi][ni][r * 2 + 0] + bn[gcol]     + bs[gcol];
                float v1 = c[mi][ni][r * 2 + 1] + bn[gcol + 1] + bs[gcol + 1];
                if (doElu) {
                    if (v0 < 0.f) v0 = expm1f(v0);
                    if (v1 < 0.f) v1 = expm1f(v1);
                }
                *(float2*)(out + (size_t)grow * DIMC + gcol) = make_float2(v0, v1);
            }
        }
    }
}

// ---------------- launch ----------------
extern "C" void kernel_launch(void* const* d_in, const int* in_sizes, int n_in,
                              void* d_out, int out_size) {
    const float* m    = (const float*)d_in[0];
    const float* vals = (const float*)d_in[1];
    const float* Wn   = (const float*)d_in[2];
    const float* bn   = (const float*)d_in[3];
    const float* Ws   = (const float*)d_in[4];
    const float* bs   = (const float*)d_in[5];
    const int*   rows = (const int*)d_in[6];   // int32: JAX default x64-disabled
    const int*   cols = (const int*)d_in[7];

    int N    = in_sizes[0] / DIMC;
    int nnz  = in_sizes[1];
    int hops = in_sizes[2] / (DIMC * DIMC);

    float *Hn, *HA, *HB;
    int *cnt, *rowptr, *woff;
    int2* edges;
    cudaGetSymbolAddress((void**)&Hn,     g_Hn);
    cudaGetSymbolAddress((void**)&HA,     g_HA);
    cudaGetSymbolAddress((void**)&HB,     g_HB);
    cudaGetSymbolAddress((void**)&edges,  g_edges);
    cudaGetSymbolAddress((void**)&cnt,    g_cnt);
    cudaGetSymbolAddress((void**)&rowptr, g_rowptr);
    cudaGetSymbolAddress((void**)&woff,   g_woff);

    // --- build CSR once, reuse across hops ---
    zero_cnt_kernel<<<(N + 255) / 256, 256>>>(cnt, N);
    hist_kernel<<<(nnz + 255) / 256, 256>>>(rows, cnt, nnz);
    scan_kernel<<<1, 1024>>>(cnt, rowptr, woff, N, nnz);
    scatter_kernel<<<(nnz + 255) / 256, 256>>>(rows, cols, vals, woff, edges, nnz);

    // --- hop loop ---
    float* out0 = (float*)d_out;
    int spmm_blocks = (N * 32 + 255) / 256;     // warp per row
    dim3 ggrid((N + 127) / 128, DIMC / 128);

    const float* Hcur = m;
    for (int i = 0; i < hops; i++) {
        spmm_kernel<<<spmm_blocks, 256>>>(Hcur, rowptr, edges, Hn, N);
        float* dst = (i == hops - 1) ? out0 : (i == 0 ? HA : HB);
        gemm_tf32_kernel<<<ggrid, 128>>>(Hn, Hcur,
                                         Wn + (size_t)i * DIMC * DIMC,
                                         Ws + (size_t)i * DIMC * DIMC,
                                         bn + (size_t)i * DIMC,
                                         bs + (size_t)i * DIMC,
                                         dst, N, i != hops - 1);
        Hcur = dst;
    }
}

// round 5
// speedup vs baseline: 2.3657x; 1.1900x over previous
#include <cuda_runtime.h>
#include <cuda_fp16.h>
#include <cuda_bf16.h>

// ---------------- constants (match problem shape) ----------------
#define NMAX      100000
#define NNZMAX    3200000
#define DIMC      256

// ---------------- device scratch (no allocations allowed) ----------------
__device__ static float  g_Hn[NMAX * DIMC];   // SpMM result per hop (fp32)
__device__ static float  g_HA[NMAX * DIMC];   // H after hop 0 (fp32, GEMM Hc)
__device__ static float  g_HB[NMAX * DIMC];   // H after hop 1
__device__ static __half g_H16[NMAX * DIMC];  // fp16 shadow of current H (SpMM gather)
__device__ static int2   g_edges[NNZMAX];     // CSR: (col, val-as-bits) sorted by row
__device__ static int    g_cnt[NMAX];
__device__ static int    g_rowptr[NMAX + 1];
__device__ static int    g_woff[NMAX];

// ---------------- CSR build ----------------
__global__ void zero_cnt_kernel(int* cnt, int N) {
    int i = blockIdx.x * blockDim.x + threadIdx.x;
    if (i < N) cnt[i] = 0;
}

__global__ void hist_kernel(const int* __restrict__ rows, int* cnt, int nnz) {
    int e = blockIdx.x * blockDim.x + threadIdx.x;
    if (e < nnz) atomicAdd(&cnt[rows[e]], 1);
}

// single-block exclusive scan over N counts (1024 threads, sequential chunks)
__global__ void scan_kernel(const int* __restrict__ cnt, int* row_ptr, int* woff,
                            int N, int nnz) {
    __shared__ int wsum[32];
    int tid = threadIdx.x;
    int CH = (N + 1023) / 1024;
    int base = tid * CH;
    int s = 0;
    for (int j = 0; j < CH; j++) {
        int i = base + j;
        if (i < N) s += cnt[i];
    }
    int v = s;
    #pragma unroll
    for (int d = 1; d < 32; d <<= 1) {
        int n = __shfl_up_sync(0xffffffffu, v, d);
        if ((tid & 31) >= d) v += n;
    }
    if ((tid & 31) == 31) wsum[tid >> 5] = v;
    __syncthreads();
    if (tid < 32) {
        int w = wsum[tid];
        #pragma unroll
        for (int d = 1; d < 32; d <<= 1) {
            int n = __shfl_up_sync(0xffffffffu, w, d);
            if (tid >= d) w += n;
        }
        wsum[tid] = w;
    }
    __syncthreads();
    int warp = tid >> 5;
    int excl = (v - s) + (warp > 0 ? wsum[warp - 1] : 0);
    int run = excl;
    for (int j = 0; j < CH; j++) {
        int i = base + j;
        if (i < N) {
            row_ptr[i] = run;
            woff[i]    = run;
            run += cnt[i];
        }
    }
    if (tid == 0) row_ptr[N] = nnz;
}

__global__ void scatter_kernel(const int* __restrict__ rows,
                               const int* __restrict__ cols,
                               const float* __restrict__ vals,
                               int* woff, int2* edges, int nnz) {
    int e = blockIdx.x * blockDim.x + threadIdx.x;
    if (e < nnz) {
        int r = rows[e];
        int p = atomicAdd(&woff[r], 1);
        edges[p] = make_int2(cols[e], __float_as_int(vals[e]));
    }
}

// ---------------- fp32 -> fp16 conversion (for the initial m) ----------------
__global__ void f2h_kernel(const float* __restrict__ src, __half* __restrict__ dst,
                           int n) {  // n = total elems / 2
    int i = blockIdx.x * blockDim.x + threadIdx.x;
    if (i < n) {
        float2 v = ((const float2*)src)[i];
        ((__half2*)dst)[i] = __floats2half2_rn(v.x, v.y);
    }
}

// ---------------- SpMM: warp per row, CSR, fp16 gather (L2-resident) --------
__global__ void spmm16_kernel(const __half* __restrict__ H,
                              const int* __restrict__ row_ptr,
                              const int2* __restrict__ edges,
                              float* __restrict__ Hn, int N) {
    int warp = (blockIdx.x * blockDim.x + threadIdx.x) >> 5;
    int lane = threadIdx.x & 31;
    if (warp >= N) return;
    int start = row_ptr[warp];
    int end   = row_ptr[warp + 1];

    float acc[8];
    #pragma unroll
    for (int i = 0; i < 8; i++) acc[i] = 0.f;

    for (int e0 = start; e0 < end; e0 += 32) {
        int idx = e0 + lane;
        int2 ed = make_int2(0, 0);
        if (idx < end) ed = edges[idx];
        int cnt = min(32, end - e0);
        for (int j = 0; j < cnt; j++) {
            int   col = __shfl_sync(0xffffffffu, ed.x, j);
            float val = __int_as_float(__shfl_sync(0xffffffffu, ed.y, j));
            // warp gathers the full 256-half row: lane reads 8 halves (16B)
            uint4 raw = ((const uint4*)(H + (size_t)col * DIMC))[lane];
            const __half2* hh = (const __half2*)&raw;
            float2 f0 = __half22float2(hh[0]);
            float2 f1 = __half22float2(hh[1]);
            float2 f2 = __half22float2(hh[2]);
            float2 f3 = __half22float2(hh[3]);
            acc[0] += val * f0.x; acc[1] += val * f0.y;
            acc[2] += val * f1.x; acc[3] += val * f1.y;
            acc[4] += val * f2.x; acc[5] += val * f2.y;
            acc[6] += val * f3.x; acc[7] += val * f3.y;
        }
    }
    float4* out = (float4*)(Hn + (size_t)warp * DIMC);
    out[lane * 2 + 0] = make_float4(acc[0], acc[1], acc[2], acc[3]);
    out[lane * 2 + 1] = make_float4(acc[4], acc[5], acc[6], acc[7]);
}

// ---------------- tf32 tensor-core GEMM ----------------
// out[M,256] = Hn@Wn^T + Hc@Ws^T + (bn+bs), optional ELU.
// K=512 logical (k<256 -> Hn/Wn, else Hc/Ws). Block tile 128x128, 4 warps
// (2x2), warp tile 64x64, BK=16, cp.async double-buffered smem.
// If out16 != nullptr, also stores the fp16 shadow for the next SpMM.
#define GSTR 20   // smem row stride in words (16 k + 4 pad) -> conflict-free frags

__device__ __forceinline__ unsigned f2tf32(float x) {
    unsigned r;
    asm("cvt.rna.tf32.f32 %0, %1;" : "=r"(r) : "f"(x));
    return r;
}

__global__ __launch_bounds__(128)
void gemm_tf32_kernel(const float* __restrict__ Hn, const float* __restrict__ Hc,
                      const float* __restrict__ Wn, const float* __restrict__ Ws,
                      const float* __restrict__ bn, const float* __restrict__ bs,
                      float* __restrict__ out, __half* __restrict__ out16,
                      int M, int doElu) {
    __shared__ float As[2][128 * GSTR];
    __shared__ float Bs[2][128 * GSTR];

    int tid  = threadIdx.x;
    int lane = tid & 31;
    int wid  = tid >> 5;
    int grp  = lane >> 2;       // 0..7
    int tig  = lane & 3;        // 0..3
    int warpM = wid >> 1;       // 0..1
    int warpN = wid & 1;        // 0..1
    int rowBase = blockIdx.x * 128;
    int colBase = blockIdx.y * 128;

    int lf = tid & 3;           // k-float4 slot (0..3 -> k 0..15)
    int lr = tid >> 2;          // 0..31 row base

    float c[4][8][4];
    #pragma unroll
    for (int mi = 0; mi < 4; mi++)
        #pragma unroll
        for (int ni = 0; ni < 8; ni++)
            #pragma unroll
            for (int r = 0; r < 4; r++) c[mi][ni][r] = 0.f;

    // issue cp.async loads for k-slab `it` into stage it&1
    auto issue = [&](int it) {
        int k0 = it * 16;
        const float* Asrc = (k0 < 256) ? Hn : Hc;
        const float* Wsrc = (k0 < 256) ? Wn : Ws;
        int kOff = k0 & 255;
        int st = it & 1;
        #pragma unroll
        for (int i = 0; i < 4; i++) {
            int row = lr + 32 * i;
            int grow = rowBase + row;
            int ok = (grow < M);
            const float* asrc = Asrc + (size_t)(ok ? grow : 0) * DIMC + kOff + lf * 4;
            unsigned adst = (unsigned)__cvta_generic_to_shared(&As[st][row * GSTR + lf * 4]);
            int asz = ok ? 16 : 0;
            asm volatile("cp.async.cg.shared.global [%0], [%1], 16, %2;\n"
                         :: "r"(adst), "l"(asrc), "r"(asz));
            const float* bsrc = Wsrc + (size_t)(colBase + row) * DIMC + kOff + lf * 4;
            unsigned bdst = (unsigned)__cvta_generic_to_shared(&Bs[st][row * GSTR + lf * 4]);
            asm volatile("cp.async.cg.shared.global [%0], [%1], 16, %2;\n"
                         :: "r"(bdst), "l"(bsrc), "r"(16));
        }
        asm volatile("cp.async.commit_group;\n");
    };

    issue(0);

    for (int it = 0; it < 32; it++) {
        if (it + 1 < 32) {
            issue(it + 1);
            asm volatile("cp.async.wait_group 1;\n");
        } else {
            asm volatile("cp.async.wait_group 0;\n");
        }
        __syncthreads();

        int st = it & 1;
        #pragma unroll
        for (int kk = 0; kk < 2; kk++) {
            unsigned a[4][4], b[8][2];
            int k = kk * 8 + tig;
            #pragma unroll
            for (int mi = 0; mi < 4; mi++) {
                int m0 = warpM * 64 + mi * 16 + grp;
                a[mi][0] = f2tf32(As[st][m0 * GSTR + k]);
                a[mi][1] = f2tf32(As[st][(m0 + 8) * GSTR + k]);
                a[mi][2] = f2tf32(As[st][m0 * GSTR + k + 4]);
                a[mi][3] = f2tf32(As[st][(m0 + 8) * GSTR + k + 4]);
            }
            #pragma unroll
            for (int ni = 0; ni < 8; ni++) {
                int n0 = warpN * 64 + ni * 8 + grp;
                b[ni][0] = f2tf32(Bs[st][n0 * GSTR + k]);
                b[ni][1] = f2tf32(Bs[st][n0 * GSTR + k + 4]);
            }
            #pragma unroll
            for (int mi = 0; mi < 4; mi++)
                #pragma unroll
                for (int ni = 0; ni < 8; ni++) {
                    asm volatile(
                        "mma.sync.aligned.m16n8k8.row.col.f32.tf32.tf32.f32 "
                        "{%0,%1,%2,%3}, {%4,%5,%6,%7}, {%8,%9}, {%0,%1,%2,%3};\n"
                        : "+f"(c[mi][ni][0]), "+f"(c[mi][ni][1]),
                          "+f"(c[mi][ni][2]), "+f"(c[mi][ni][3])
                        : "r"(a[mi][0]), "r"(a[mi][1]), "r"(a[mi][2]), "r"(a[mi][3]),
                          "r"(b[ni][0]), "r"(b[ni][1]));
                }
        }
        __syncthreads();
    }

    // epilogue: bias + optional ELU (+ fp16 shadow for next SpMM)
    #pragma unroll
    for (int mi = 0; mi < 4; mi++) {
        #pragma unroll
        for (int r = 0; r < 2; r++) {
            int grow = rowBase + warpM * 64 + mi * 16 + grp + r * 8;
            if (grow >= M) continue;
            #pragma unroll
            for (int ni = 0; ni < 8; ni++) {
                int gcol = colBase + warpN * 64 + ni * 8 + tig * 2;
                float v0 = c[mi][ni][r * 2 + 0] + bn[gcol]     + bs[gcol];
                float v1 = c[mi][ni][r * 2 + 1] + bn[gcol + 1] + bs[gcol + 1];
                if (doElu) {
                    if (v0 < 0.f) v0 = expm1f(v0);
                    if (v1 < 0.f) v1 = expm1f(v1);
                }
                *(float2*)(out + (size_t)grow * DIMC + gcol) = make_float2(v0, v1);
                if (out16)
                    *(__half2*)(out16 + (size_t)grow * DIMC + gcol) =
                        __floats2half2_rn(v0, v1);
            }
        }
    }
}

// ---------------- launch ----------------
extern "C" void kernel_launch(void* const* d_in, const int* in_sizes, int n_in,
                              void* d_out, int out_size) {
    const float* m    = (const float*)d_in[0];
    const float* vals = (const float*)d_in[1];
    const float* Wn   = (const float*)d_in[2];
    const float* bn   = (const float*)d_in[3];
    const float* Ws   = (const float*)d_in[4];
    const float* bs   = (const float*)d_in[5];
    const int*   rows = (const int*)d_in[6];   // int32: JAX default x64-disabled
    const int*   cols = (const int*)d_in[7];

    int N    = in_sizes[0] / DIMC;
    int nnz  = in_sizes[1];
    int hops = in_sizes[2] / (DIMC * DIMC);

    float *Hn, *HA, *HB;
    __half* H16;
    int *cnt, *rowptr, *woff;
    int2* edges;
    cudaGetSymbolAddress((void**)&Hn,     g_Hn);
    cudaGetSymbolAddress((void**)&HA,     g_HA);
    cudaGetSymbolAddress((void**)&HB,     g_HB);
    cudaGetSymbolAddress((void**)&H16,    g_H16);
    cudaGetSymbolAddress((void**)&edges,  g_edges);
    cudaGetSymbolAddress((void**)&cnt,    g_cnt);
    cudaGetSymbolAddress((void**)&rowptr, g_rowptr);
    cudaGetSymbolAddress((void**)&woff,   g_woff);

    // --- build CSR once, reuse across hops ---
    zero_cnt_kernel<<<(N + 255) / 256, 256>>>(cnt, N);
    hist_kernel<<<(nnz + 255) / 256, 256>>>(rows, cnt, nnz);
    scan_kernel<<<1, 1024>>>(cnt, rowptr, woff, N, nnz);
    scatter_kernel<<<(nnz + 255) / 256, 256>>>(rows, cols, vals, woff, edges, nnz);

    // --- fp16 shadow of initial H ---
    int nh2 = N * DIMC / 2;
    f2h_kernel<<<(nh2 + 255) / 256, 256>>>(m, H16, nh2);

    // --- hop loop ---
    float* out0 = (float*)d_out;
    int spmm_blocks = (N * 32 + 255) / 256;     // warp per row
    dim3 ggrid((N + 127) / 128, DIMC / 128);

    const float* Hcur = m;
    for (int i = 0; i < hops; i++) {
        spmm16_kernel<<<spmm_blocks, 256>>>(H16, rowptr, edges, Hn, N);
        int last = (i == hops - 1);
        float* dst = last ? out0 : (i == 0 ? HA : HB);
        gemm_tf32_kernel<<<ggrid, 128>>>(Hn, Hcur,
                                         Wn + (size_t)i * DIMC * DIMC,
                                         Ws + (size_t)i * DIMC * DIMC,
                                         bn + (size_t)i * DIMC,
                                         bs + (size_t)i * DIMC,
                                         dst, last ? (__half*)nullptr : H16,
                                         N, !last);
        Hcur = dst;
    }
}